// round 3
// baseline (speedup 1.0000x reference)
#include <cuda_runtime.h>
#include <math.h>

#define CC   16
#define DIMN 16
#define LL   6

// ---------------- device-global precomputed params ----------------
__device__ float g_alpha[LL * CC];
__device__ float g_Linv[CC * DIMN * DIMN];
__device__ float g_hld[CC];
__device__ int   g_ident;

// ---------------- f32x2 packed helpers (sm_103a) -------------------
typedef unsigned long long u64;

__device__ __forceinline__ u64 pk2(float lo, float hi) {
    u64 r;
    asm("mov.b64 %0, {%1, %2};" : "=l"(r) : "f"(lo), "f"(hi));
    return r;
}
__device__ __forceinline__ void up2(float& lo, float& hi, u64 v) {
    asm("mov.b64 {%0, %1}, %2;" : "=f"(lo), "=f"(hi) : "l"(v));
}
__device__ __forceinline__ u64 ffma2(u64 a, u64 b, u64 c) {
    u64 d;
    asm("fma.rn.f32x2 %0, %1, %2, %3;" : "=l"(d) : "l"(a), "l"(b), "l"(c));
    return d;
}
__device__ __forceinline__ float fast_sqrt(float x) {
    float r;
    asm("sqrt.approx.f32 %0, %1;" : "=f"(r) : "f"(x));
    return r;
}
__device__ __forceinline__ float fast_rcp(float x) {
    float r;
    asm("rcp.approx.f32 %0, %1;" : "=f"(r) : "f"(x));
    return r;
}

// ---------------- setup: alpha = exp(log_alpha); Cholesky of cov ----------------
// 1 block, 32 threads. With the actual inputs cov == I, so the Cholesky branch
// never runs; it exists for generality/correctness under arbitrary cov.
__global__ void setup_kernel(const float* __restrict__ log_alpha,
                             const float* __restrict__ cov) {
    int t = threadIdx.x;
    for (int i = t; i < LL * CC; i += 32) g_alpha[i] = expf(log_alpha[i]);

    int c = t;
    bool ident = true;
    if (c < CC) {
        const float* A = cov + c * DIMN * DIMN;
        for (int i = 0; i < DIMN && ident; i++) {
            for (int j = 0; j < DIMN; j++) {
                float e = (i == j) ? 1.0f : 0.0f;
                if (A[i * DIMN + j] != e) { ident = false; break; }
            }
        }
    }
    unsigned b = __ballot_sync(0xFFFFFFFFu, ident);
    bool all_ident = (b == 0xFFFFFFFFu);
    if (t == 0) g_ident = all_ident ? 1 : 0;
    if (c >= CC) return;

    if (all_ident) {
        for (int i = 0; i < DIMN; i++)
            for (int j = 0; j < DIMN; j++)
                g_Linv[(c * DIMN + i) * DIMN + j] = (i == j) ? 1.0f : 0.0f;
        g_hld[c] = 0.0f;
        return;
    }

    // General Cholesky + lower-triangular inverse (slow path, rarely taken).
    float Lm[DIMN][DIMN];
    const float* A = cov + c * DIMN * DIMN;
    #pragma unroll 1
    for (int j = 0; j < DIMN; j++) {
        float s = A[j * DIMN + j];
        #pragma unroll 1
        for (int k = 0; k < j; k++) s -= Lm[j][k] * Lm[j][k];
        float d = sqrtf(s);
        Lm[j][j] = d;
        float inv = 1.0f / d;
        #pragma unroll 1
        for (int i = j + 1; i < DIMN; i++) {
            float s2 = A[i * DIMN + j];
            #pragma unroll 1
            for (int k = 0; k < j; k++) s2 -= Lm[i][k] * Lm[j][k];
            Lm[i][j] = s2 * inv;
        }
    }
    float hld = 0.0f;
    #pragma unroll 1
    for (int j = 0; j < DIMN; j++) hld += logf(Lm[j][j]);
    g_hld[c] = hld;

    float Li[DIMN][DIMN];
    #pragma unroll 1
    for (int j = 0; j < DIMN; j++) {
        for (int i = 0; i < DIMN; i++) Li[i][j] = 0.0f;
        Li[j][j] = 1.0f / Lm[j][j];
        #pragma unroll 1
        for (int i = j + 1; i < DIMN; i++) {
            float s3 = 0.0f;
            #pragma unroll 1
            for (int k = j; k < i; k++) s3 += Lm[i][k] * Li[k][j];
            Li[i][j] = -s3 / Lm[i][i];
        }
    }
    for (int i = 0; i < DIMN; i++)
        for (int j = 0; j < DIMN; j++)
            g_Linv[(c * DIMN + i) * DIMN + j] = Li[i][j];
}

// ---------------- main density kernel ----------------
__device__ __forceinline__ float compute_one(
    int c, const u64* zb,
    const float* s_z0, const float* s_ab, const float* s_mean,
    const float* s_hld, const float* s_Linv, int ident, u64 M1)
{
    u64 zc[8];
    #pragma unroll
    for (int k = 0; k < 8; k++) zc[k] = zb[k];

    float prod = 1.0f;
    #pragma unroll
    for (int l = 0; l < LL; l++) {
        const float2* z0p = (const float2*)&s_z0[(l * CC + c) * DIMN];
        u64 s[8];
        u64 acc = 0ull;  // (+0.f, +0.f)
        #pragma unroll
        for (int k = 0; k < 8; k++) {
            float2 tz = z0p[k];
            u64 z0k = pk2(tz.x, tz.y);
            s[k] = ffma2(z0k, M1, zc[k]);     // s = zc - z0
            acc  = ffma2(s[k], s[k], acc);    // r^2 accumulation
        }
        float alo, ahi; up2(alo, ahi, acc);
        float r2 = fmaxf(alo + ahi, 1e-24f);
        float r  = fast_sqrt(r2);
        float al = s_ab[l * CC + c];
        float be = s_ab[LL * CC + l * CC + c];
        float u  = al + r;
        float h  = fast_rcp(u);
        float bh = be * h;
        float f1 = 1.0f + bh;
        float f2 = fmaf(al * be, h * h, 1.0f);   // 1 + bh - beta*r*h^2 == 1 + alpha*beta*h^2
        float p2 = f1 * f1, p4 = p2 * p2, p8 = p4 * p4;
        float p15 = p8 * p4 * p2 * f1;           // (1+bh)^(dim-1)
        prod *= p15 * f2;
        u64 bh2 = pk2(bh, bh);
        #pragma unroll
        for (int k = 0; k < 8; k++) zc[k] = ffma2(bh2, s[k], zc[k]);  // z += bh*(z-z0)
    }

    const float2* mp = (const float2*)&s_mean[c * DIMN];
    float q;
    if (ident) {
        u64 accq = 0ull;
        #pragma unroll
        for (int k = 0; k < 8; k++) {
            float2 tm = mp[k];
            u64 mk = pk2(tm.x, tm.y);
            u64 d  = ffma2(mk, M1, zc[k]);    // diff = zk - mean
            accq   = ffma2(d, d, accq);
        }
        float qlo, qhi; up2(qlo, qhi, accq);
        q = qlo + qhi;
    } else {
        float dr[DIMN];
        #pragma unroll
        for (int k = 0; k < 8; k++) {
            float2 tm = mp[k];
            float lo, hi; up2(lo, hi, zc[k]);
            dr[2 * k]     = lo - tm.x;
            dr[2 * k + 1] = hi - tm.y;
        }
        q = 0.0f;
        const float* Lp = &s_Linv[c * DIMN * DIMN];
        #pragma unroll 1
        for (int j = 0; j < DIMN; j++) {
            float sj = 0.0f;
            #pragma unroll 1
            for (int i = 0; i <= j; i++) sj = fmaf(Lp[j * DIMN + i], dr[i], sj);
            q = fmaf(sj, sj, q);
        }
    }

    // -0.5*(dim*log(2pi) + q) - half_logdet + sum_log_det_jac
    const float HALF_DIM_LOG2PI = 14.7030165f;  // 0.5 * 16 * log(2*pi)
    float v = fmaf(-0.5f, q, -HALF_DIM_LOG2PI) - s_hld[c] + __logf(prod);
    if (v != v) v = __int_as_float(0xff800000);  // NaN -> -inf
    return v;
}

__global__ void __launch_bounds__(256)
density_kernel(const float* __restrict__ z, const float* __restrict__ z0,
               const float* __restrict__ beta, const float* __restrict__ mean,
               float* __restrict__ out, int N)
{
    __shared__ float s_z0[LL * CC * DIMN];      // 1536
    __shared__ float s_ab[2 * LL * CC];         // alpha | beta
    __shared__ float s_mean[CC * DIMN];         // 256
    __shared__ float s_hld[CC];
    __shared__ float s_Linv[CC * DIMN * DIMN];  // 4096 (only filled when !ident)

    int t = threadIdx.x;
    for (int i = t; i < LL * CC * DIMN; i += 256) s_z0[i] = z0[i];
    for (int i = t; i < LL * CC; i += 256) {
        s_ab[i] = g_alpha[i];
        s_ab[LL * CC + i] = beta[i];
    }
    for (int i = t; i < CC * DIMN; i += 256) s_mean[i] = mean[i];
    if (t < CC) s_hld[t] = g_hld[t];
    int ident = g_ident;
    if (!ident)
        for (int i = t; i < CC * DIMN * DIMN; i += 256) s_Linv[i] = g_Linv[i];
    __syncthreads();

    int n = blockIdx.x * 256 + t;
    if (n >= N) return;

    // Load z row once: 4 x LDG.128, pack to 8 f32x2
    const float4* zrow = (const float4*)(z + (size_t)n * DIMN);
    float4 q0 = zrow[0], q1 = zrow[1], q2 = zrow[2], q3 = zrow[3];
    u64 zb[8];
    zb[0] = pk2(q0.x, q0.y); zb[1] = pk2(q0.z, q0.w);
    zb[2] = pk2(q1.x, q1.y); zb[3] = pk2(q1.z, q1.w);
    zb[4] = pk2(q2.x, q2.y); zb[5] = pk2(q2.z, q2.w);
    zb[6] = pk2(q3.x, q3.y); zb[7] = pk2(q3.z, q3.w);
    const u64 M1 = pk2(-1.0f, -1.0f);

    float4* op = (float4*)(out + (size_t)n * CC);
    #pragma unroll 1
    for (int cg = 0; cg < 4; cg++) {
        int cbase = cg * 4;
        float r0 = compute_one(cbase + 0, zb, s_z0, s_ab, s_mean, s_hld, s_Linv, ident, M1);
        float r1 = compute_one(cbase + 1, zb, s_z0, s_ab, s_mean, s_hld, s_Linv, ident, M1);
        float r2 = compute_one(cbase + 2, zb, s_z0, s_ab, s_mean, s_hld, s_Linv, ident, M1);
        float r3 = compute_one(cbase + 3, zb, s_z0, s_ab, s_mean, s_hld, s_Linv, ident, M1);
        op[cg] = make_float4(r0, r1, r2, r3);
    }
}

// ---------------- launch ----------------
extern "C" void kernel_launch(void* const* d_in, const int* in_sizes, int n_in,
                              void* d_out, int out_size) {
    const float* z    = (const float*)d_in[0];
    const float* z0   = (const float*)d_in[1];
    const float* la   = (const float*)d_in[2];
    const float* be   = (const float*)d_in[3];
    const float* mean = (const float*)d_in[4];
    const float* cov  = (const float*)d_in[5];
    float* out = (float*)d_out;

    int N = in_sizes[0] / DIMN;

    setup_kernel<<<1, 32>>>(la, cov);
    int blocks = (N + 255) / 256;
    density_kernel<<<blocks, 256>>>(z, z0, be, mean, out, N);
}

// round 5
// speedup vs baseline: 2.5301x; 2.5301x over previous
#include <cuda_runtime.h>
#include <math.h>

#define CC   16
#define DIMN 16
#define LL   6

typedef unsigned long long u64;

// ---------------- device-global precomputed params ----------------
__device__ u64    g_negD[LL * CC * 8];   // -(z0_l - z0_{l-1}) packed f32x2; l=0: -z0_0
__device__ u64    g_m5[CC * 8];          // z0_5 - mean, packed f32x2
__device__ float4 g_par[LL * CC];        // (alpha, beta, alpha*beta, 0)
__device__ float  g_Linv[CC * DIMN * DIMN];
__device__ float  g_hld[CC];
__device__ int    g_ident;

// ---------------- f32x2 packed helpers (sm_103a) -------------------
__device__ __forceinline__ u64 pk2(float lo, float hi) {
    u64 r; asm("mov.b64 %0, {%1, %2};" : "=l"(r) : "f"(lo), "f"(hi)); return r;
}
__device__ __forceinline__ void up2(float& lo, float& hi, u64 v) {
    asm("mov.b64 {%0, %1}, %2;" : "=f"(lo), "=f"(hi) : "l"(v));
}
__device__ __forceinline__ u64 ffma2(u64 a, u64 b, u64 c) {
    u64 d; asm("fma.rn.f32x2 %0, %1, %2, %3;" : "=l"(d) : "l"(a), "l"(b), "l"(c)); return d;
}
__device__ __forceinline__ u64 add2(u64 a, u64 b) {
    u64 d; asm("add.rn.f32x2 %0, %1, %2;" : "=l"(d) : "l"(a), "l"(b)); return d;
}
__device__ __forceinline__ float fast_sqrt(float x) {
    float r; asm("sqrt.approx.f32 %0, %1;" : "=f"(r) : "f"(x)); return r;
}
__device__ __forceinline__ float fast_rcp(float x) {
    float r; asm("rcp.approx.f32 %0, %1;" : "=f"(r) : "f"(x)); return r;
}
__device__ __forceinline__ float hsum2(u64 a, u64 b) {
    u64 e = add2(a, b);
    float lo, hi; up2(lo, hi, e);
    return lo + hi;
}
__device__ __forceinline__ float pow15(float x) {
    float x2 = x * x, x4 = x2 * x2, x8 = x4 * x4;
    return x8 * x4 * x2 * x;
}

// per-layer scalar tail: r^2 -> f1, accumulate products
__device__ __forceinline__ void layer_scalar(u64 e0, u64 e1, float4 pr,
                                             float& f1, float& P1, float& P2) {
    float r2 = hsum2(e0, e1);
    float r  = fast_sqrt(r2);
    float h  = fast_rcp(pr.x + r);          // 1/(alpha + r)
    f1 = fmaf(pr.y, h, 1.0f);               // 1 + beta*h
    float f2 = fmaf(pr.z, h * h, 1.0f);     // 1 + alpha*beta*h^2
    P1 *= f1;
    P2 *= f2;
}

// ---------------- setup kernel ----------------
__global__ void setup_kernel(const float* __restrict__ la, const float* __restrict__ be,
                             const float* __restrict__ z0, const float* __restrict__ mean,
                             const float* __restrict__ cov) {
    __shared__ int s_bad;
    int t = threadIdx.x;
    if (t == 0) s_bad = 0;
    __syncthreads();

    for (int i = t; i < LL * CC; i += 256) {
        float a = expf(la[i]);
        float b = be[i];
        g_par[i] = make_float4(a, b, a * b, 0.0f);
    }
    for (int i = t; i < LL * CC * 8; i += 256) {
        int l = i / (CC * 8), rem = i % (CC * 8), c = rem / 8, k = rem % 8;
        int base = (l * CC + c) * DIMN + 2 * k;
        float lo = -z0[base], hi = -z0[base + 1];
        if (l > 0) {
            int pb = ((l - 1) * CC + c) * DIMN + 2 * k;
            lo += z0[pb]; hi += z0[pb + 1];
        }
        g_negD[i] = pk2(lo, hi);
    }
    for (int i = t; i < CC * 8; i += 256) {
        int c = i / 8, k = i % 8;
        int b5 = (5 * CC + c) * DIMN + 2 * k;
        float lo = z0[b5]     - mean[c * DIMN + 2 * k];
        float hi = z0[b5 + 1] - mean[c * DIMN + 2 * k + 1];
        g_m5[i] = pk2(lo, hi);
    }

    int bad = 0;
    for (int i = t; i < CC * DIMN * DIMN; i += 256) {
        float e = (((i % (DIMN * DIMN)) % (DIMN + 1)) == 0) ? 1.0f : 0.0f;
        if (cov[i] != e) bad = 1;
    }
    if (bad) atomicOr(&s_bad, 1);
    __syncthreads();
    int id = (s_bad == 0) ? 1 : 0;
    if (t == 0) g_ident = id;

    int c = t;
    if (c < CC) {
        if (id) { g_hld[c] = 0.0f; return; }
        // general Cholesky + triangular inverse (cold path)
        float Lm[DIMN][DIMN];
        const float* A = cov + c * DIMN * DIMN;
        #pragma unroll 1
        for (int j = 0; j < DIMN; j++) {
            float s = A[j * DIMN + j];
            #pragma unroll 1
            for (int k = 0; k < j; k++) s -= Lm[j][k] * Lm[j][k];
            float d = sqrtf(s);
            Lm[j][j] = d;
            float inv = 1.0f / d;
            #pragma unroll 1
            for (int i = j + 1; i < DIMN; i++) {
                float s2 = A[i * DIMN + j];
                #pragma unroll 1
                for (int k = 0; k < j; k++) s2 -= Lm[i][k] * Lm[j][k];
                Lm[i][j] = s2 * inv;
            }
        }
        float hld = 0.0f;
        #pragma unroll 1
        for (int j = 0; j < DIMN; j++) hld += logf(Lm[j][j]);
        g_hld[c] = hld;

        float Li[DIMN][DIMN];
        #pragma unroll 1
        for (int j = 0; j < DIMN; j++) {
            for (int i = 0; i < DIMN; i++) Li[i][j] = 0.0f;
            Li[j][j] = 1.0f / Lm[j][j];
            #pragma unroll 1
            for (int i = j + 1; i < DIMN; i++) {
                float s3 = 0.0f;
                #pragma unroll 1
                for (int k = j; k < i; k++) s3 += Lm[i][k] * Li[k][j];
                Li[i][j] = -s3 / Lm[i][i];
            }
        }
        for (int i = 0; i < DIMN; i++)
            for (int j = 0; j < DIMN; j++)
                g_Linv[(c * DIMN + i) * DIMN + j] = Li[i][j];
    }
}

// ---------------- main density kernel ----------------
__global__ void __launch_bounds__(128)
density_kernel(const float* __restrict__ z, float* __restrict__ out, int N)
{
    __shared__ u64    s_negD[LL * CC * 8];     // 6 KB
    __shared__ float4 s_par[LL * CC];          // 1.5 KB
    __shared__ u64    s_m5[CC * 8];            // 1 KB
    __shared__ float  s_hld[CC];
    __shared__ float  s_Linv[CC * DIMN * DIMN];// 16 KB (filled only if !ident)

    int t = threadIdx.x;
    for (int i = t; i < LL * CC * 8; i += 128) s_negD[i] = g_negD[i];
    for (int i = t; i < LL * CC; i += 128)     s_par[i]  = g_par[i];
    for (int i = t; i < CC * 8; i += 128)      s_m5[i]   = g_m5[i];
    if (t < CC) s_hld[t] = g_hld[t];
    int ident = g_ident;
    if (!ident)
        for (int i = t; i < CC * DIMN * DIMN; i += 128) s_Linv[i] = g_Linv[i];
    __syncthreads();

    int n = blockIdx.x * 128 + t;
    if (n >= N) return;

    const float4* zrow = (const float4*)(z + (size_t)n * DIMN);
    float4 q0 = zrow[0], q1 = zrow[1], q2 = zrow[2], q3 = zrow[3];
    u64 zb[8];
    zb[0] = pk2(q0.x, q0.y); zb[1] = pk2(q0.z, q0.w);
    zb[2] = pk2(q1.x, q1.y); zb[3] = pk2(q1.z, q1.w);
    zb[4] = pk2(q2.x, q2.y); zb[5] = pk2(q2.z, q2.w);
    zb[6] = pk2(q3.x, q3.y); zb[7] = pk2(q3.z, q3.w);

    const float HALF_DIM_LOG2PI = 14.7030165f;  // 0.5 * 16 * log(2*pi)
    float2* op = (float2*)(out + (size_t)n * CC);

    #pragma unroll 1
    for (int cp = 0; cp < 8; cp++) {
        int c0 = 2 * cp, c1 = c0 + 1;
        const u64* dA = &s_negD[c0 * 8];    // stride per layer: CC*8 = 128 u64
        const u64* dB = &s_negD[c1 * 8];

        u64 sA[8], sB[8];
        float f1A, f1B;
        float P1A = 1.0f, P2A = 1.0f, P1B = 1.0f, P2B = 1.0f;

        // ---- layer 0: s = z - z0_0 ----
        {
            u64 e0A = 0ull, e1A = 0ull, e0B = 0ull, e1B = 0ull;
            #pragma unroll
            for (int k = 0; k < 8; k++) {
                sA[k] = add2(zb[k], dA[k]);
                sB[k] = add2(zb[k], dB[k]);
                if (k & 1) { e1A = ffma2(sA[k], sA[k], e1A); e1B = ffma2(sB[k], sB[k], e1B); }
                else       { e0A = ffma2(sA[k], sA[k], e0A); e0B = ffma2(sB[k], sB[k], e0B); }
            }
            layer_scalar(e0A, e1A, s_par[c0], f1A, P1A, P2A);
            layer_scalar(e0B, e1B, s_par[c1], f1B, P1B, P2B);
        }

        // ---- layers 1..5: s' = f1*s - (z0_l - z0_{l-1}) ----
        #pragma unroll
        for (int l = 1; l < LL; l++) {
            u64 f1A2 = pk2(f1A, f1A);
            u64 f1B2 = pk2(f1B, f1B);
            u64 e0A = 0ull, e1A = 0ull, e0B = 0ull, e1B = 0ull;
            #pragma unroll
            for (int k = 0; k < 8; k++) {
                sA[k] = ffma2(f1A2, sA[k], dA[l * CC * 8 + k]);
                sB[k] = ffma2(f1B2, sB[k], dB[l * CC * 8 + k]);
                if (k & 1) { e1A = ffma2(sA[k], sA[k], e1A); e1B = ffma2(sB[k], sB[k], e1B); }
                else       { e0A = ffma2(sA[k], sA[k], e0A); e0B = ffma2(sB[k], sB[k], e0B); }
            }
            layer_scalar(e0A, e1A, s_par[l * CC + c0], f1A, P1A, P2A);
            layer_scalar(e0B, e1B, s_par[l * CC + c1], f1B, P1B, P2B);
        }

        // ---- final: diff = zK - mean = f1_5*s_5 + (z0_5 - mean) ----
        u64 f1A2 = pk2(f1A, f1A);
        u64 f1B2 = pk2(f1B, f1B);
        float qA, qB;
        if (ident) {
            u64 a0 = 0ull, a1 = 0ull, b0 = 0ull, b1 = 0ull;
            #pragma unroll
            for (int k = 0; k < 8; k++) {
                u64 da = ffma2(f1A2, sA[k], s_m5[c0 * 8 + k]);
                u64 db = ffma2(f1B2, sB[k], s_m5[c1 * 8 + k]);
                if (k & 1) { a1 = ffma2(da, da, a1); b1 = ffma2(db, db, b1); }
                else       { a0 = ffma2(da, da, a0); b0 = ffma2(db, db, b0); }
            }
            qA = hsum2(a0, a1);
            qB = hsum2(b0, b1);
        } else {
            float drA[DIMN], drB[DIMN];
            #pragma unroll
            for (int k = 0; k < 8; k++) {
                u64 da = ffma2(f1A2, sA[k], s_m5[c0 * 8 + k]);
                u64 db = ffma2(f1B2, sB[k], s_m5[c1 * 8 + k]);
                up2(drA[2 * k], drA[2 * k + 1], da);
                up2(drB[2 * k], drB[2 * k + 1], db);
            }
            qA = 0.0f; qB = 0.0f;
            const float* LpA = &s_Linv[c0 * DIMN * DIMN];
            const float* LpB = &s_Linv[c1 * DIMN * DIMN];
            #pragma unroll 1
            for (int j = 0; j < DIMN; j++) {
                float sa = 0.0f, sb = 0.0f;
                #pragma unroll 1
                for (int i = 0; i <= j; i++) {
                    sa = fmaf(LpA[j * DIMN + i], drA[i], sa);
                    sb = fmaf(LpB[j * DIMN + i], drB[i], sb);
                }
                qA = fmaf(sa, sa, qA);
                qB = fmaf(sb, sb, qB);
            }
        }

        // log_det_jac total = log(P1^15 * P2)
        float gA = pow15(P1A) * P2A;
        float gB = pow15(P1B) * P2B;
        float vA = fmaf(-0.5f, qA, -HALF_DIM_LOG2PI) - s_hld[c0] + __logf(gA);
        float vB = fmaf(-0.5f, qB, -HALF_DIM_LOG2PI) - s_hld[c1] + __logf(gB);
        if (vA != vA) vA = __int_as_float(0xff800000);
        if (vB != vB) vB = __int_as_float(0xff800000);
        op[cp] = make_float2(vA, vB);
    }
}

// ---------------- launch ----------------
extern "C" void kernel_launch(void* const* d_in, const int* in_sizes, int n_in,
                              void* d_out, int out_size) {
    const float* z    = (const float*)d_in[0];
    const float* z0   = (const float*)d_in[1];
    const float* la   = (const float*)d_in[2];
    const float* be   = (const float*)d_in[3];
    const float* mean = (const float*)d_in[4];
    const float* cov  = (const float*)d_in[5];
    float* out = (float*)d_out;

    int N = in_sizes[0] / DIMN;

    setup_kernel<<<1, 256>>>(la, be, z0, mean, cov);
    int blocks = (N + 127) / 128;
    density_kernel<<<blocks, 128>>>(z, out, N);
}